// round 2
// baseline (speedup 1.0000x reference)
#include <cuda_runtime.h>

// ---------------- problem constants ----------------
#define N_IMG 2
#define A_ 9
#define C_ 80
#define H_ 100
#define W_ 152
#define HW_ 15200           // H*W
#define CHW_ (C_*HW_)       // 1,216,000
#define ACHW 10944000       // A*C*H*W per image
#define REG_PER_IMG (A_*4*HW_)
#define TOPN 1000
#define POSTN 100
#define CAP 16384
#define NBINS 4096
#define CHUNK 512                 // floats per chunk
#define CPI (ACHW/CHUNK)          // 21375 chunks per image
#define NPAIRS (CPI/2)            // 10687 (CPI is odd; 1 tail chunk)
#define NGROUPS ((CPI+31)/32)     // 668
#define THRESH_LOGIT -2.9444389791664403f   // log(0.05/0.95)
#define BBOX_CLIP 4.1351665567423556f       // log(1000/16)
#define IMW1 1215.0f
#define IMH1 799.0f
#define NMS_T 0.5f
#define FULLMASK 0xffffffffu

// ---------------- device scratch (static, no allocs) ----------------
__device__ unsigned            g_hist[N_IMG][NBINS];
__device__ unsigned            g_chunkmax[N_IMG][CPI];
__device__ int                 g_count[N_IMG];
__device__ int                 g_pivot[N_IMG];
__device__ unsigned long long  g_cand[N_IMG][CAP];
__device__ float               g_boxes[N_IMG][TOPN][4];
__device__ float4              g_obox[N_IMG][TOPN];
__device__ float               g_area[N_IMG][TOPN];
__device__ float               g_scores[N_IMG][TOPN];
__device__ int                 g_labels[N_IMG][TOPN];
__device__ unsigned            g_validmask[N_IMG][32];
__device__ unsigned            g_iou[N_IMG][TOPN][32];
__device__ unsigned            g_keepw[N_IMG][32];
__device__ int                 g_totkept[N_IMG];

// monotone mapping: float bits -> unsigned preserving > ordering
__device__ __forceinline__ unsigned mono_of(float x) {
    unsigned b = __float_as_uint(x);
    return b ^ ((unsigned)((int)b >> 31) | 0x80000000u);
}

__device__ __forceinline__ void unpack4(const float4* w, float* v) {
#pragma unroll
    for (int e = 0; e < 4; e++) {
        v[e * 4 + 0] = w[e].x; v[e * 4 + 1] = w[e].y;
        v[e * 4 + 2] = w[e].z; v[e * 4 + 3] = w[e].w;
    }
}

// histogram + max for one 512-float chunk already held in registers (16 vals/lane)
__device__ __forceinline__ unsigned chunk_hist(const float* vv, int lane, unsigned* sh) {
    unsigned mmax = 0u;
#pragma unroll
    for (int e = 0; e < 16; e++) {
        unsigned mono = mono_of(vv[e]);
        if (mono > mmax) mmax = mono;
        bool ab = vv[e] > THRESH_LOGIT;
        unsigned bal = __ballot_sync(FULLMASK, ab);
        if (ab) {
            unsigned bin = mono >> 20;
            unsigned grp = __match_any_sync(bal, bin);
            if (__ffs(grp) - 1 == lane)
                atomicAdd(&sh[bin], (unsigned)__popc(grp));
        }
    }
    return __reduce_max_sync(FULLMASK, mmax);
}

// ---------------- 1: histogram + per-chunk max (single DRAM sweep) --------
__global__ __launch_bounds__(256) void hist_kernel(const float* __restrict__ cls) {
    __shared__ unsigned sh[NBINS];
    for (int i = threadIdx.x; i < NBINS; i += blockDim.x) sh[i] = 0u;
    __syncthreads();
    const int n = blockIdx.y;
    const int lane = threadIdx.x & 31;
    const int gw = (blockIdx.x * blockDim.x + threadIdx.x) >> 5;
    const int nwarps = (gridDim.x * blockDim.x) >> 5;
    const float4* base = reinterpret_cast<const float4*>(cls + (size_t)n * ACHW);

    for (int pp = gw; pp < NPAIRS; pp += nwarps) {
        const float4* p = base + (size_t)pp * 256;
        float4 w[8];
#pragma unroll
        for (int e = 0; e < 8; e++) w[e] = p[e * 32 + lane];   // 8 loads in flight
        float va[16], vb[16];
        unpack4(w, va);
        unpack4(w + 4, vb);
        unsigned mx0 = chunk_hist(va, lane, sh);
        unsigned mx1 = chunk_hist(vb, lane, sh);
        if (lane == 0) {
            g_chunkmax[n][pp * 2 + 0] = mx0;
            g_chunkmax[n][pp * 2 + 1] = mx1;
        }
    }
    // tail chunk (CPI is odd)
    if (gw == 0) {
        const float4* p = base + (size_t)(CPI - 1) * 128;
        float4 w[4];
#pragma unroll
        for (int e = 0; e < 4; e++) w[e] = p[e * 32 + lane];
        float va[16];
        unpack4(w, va);
        unsigned mx = chunk_hist(va, lane, sh);
        if (lane == 0) g_chunkmax[n][CPI - 1] = mx;
    }
    __syncthreads();
    for (int i = threadIdx.x; i < NBINS; i += blockDim.x) {
        unsigned v = sh[i];
        if (v) atomicAdd(&g_hist[n][i], v);
    }
}

// ---------------- 2: find pivot bucket, then reset hist/count ------------
__global__ void pivot_kernel() {
    __shared__ unsigned cs[1024];
    __shared__ int s_min;
    const int t = threadIdx.x;
    for (int n = 0; n < N_IMG; n++) {
        if (t == 0) s_min = NBINS;
        __syncthreads();
        unsigned local[4];
        unsigned sum = 0;
#pragma unroll
        for (int e = 0; e < 4; e++) {
            int r = t * 4 + e;                       // reversed position
            unsigned v = g_hist[n][NBINS - 1 - r];
            local[e] = v; sum += v;
        }
        cs[t] = sum;
        __syncthreads();
        for (int off = 1; off < 1024; off <<= 1) {
            unsigned v = (t >= off) ? cs[t - off] : 0u;
            __syncthreads();
            cs[t] += v;
            __syncthreads();
        }
        unsigned run = (t == 0) ? 0u : cs[t - 1];
        int found = -1;
#pragma unroll
        for (int e = 0; e < 4; e++) {
            run += local[e];
            if (found < 0 && run >= TOPN) found = t * 4 + e;
        }
        if (found >= 0) atomicMin(&s_min, found);
        __syncthreads();
        if (t == 0) g_pivot[n] = (s_min >= NBINS) ? 0 : (NBINS - 1 - s_min);
        __syncthreads();
    }
    // reset per-replay state for this replay / next replay
    for (int i = t; i < N_IMG * NBINS; i += blockDim.x)
        ((unsigned*)g_hist)[i] = 0u;
    if (t < N_IMG) g_count[t] = 0;
}

// ---------------- 3: collect candidates, skipping pruned chunks ----------
__global__ __launch_bounds__(256) void collect_kernel(const float* __restrict__ cls) {
    const int n = blockIdx.y;
    const unsigned pivot_base = (unsigned)g_pivot[n] << 20;
    const int lane = threadIdx.x & 31;
    const int gw = (blockIdx.x * blockDim.x + threadIdx.x) >> 5;
    const int nwarps = (gridDim.x * blockDim.x) >> 5;
    const float4* base = reinterpret_cast<const float4*>(cls + (size_t)n * ACHW);

    for (int g = gw; g < NGROUPS; g += nwarps) {
        int chbase = g * 32;
        int ch_l = chbase + lane;
        bool active = (ch_l < CPI) && (g_chunkmax[n][ch_l] >= pivot_base);
        unsigned act = __ballot_sync(FULLMASK, active);
        while (act) {
            int c = __ffs(act) - 1;
            act &= act - 1;
            int ch = chbase + c;
            const float4* p = base + (size_t)ch * 128;
#pragma unroll
            for (int e = 0; e < 4; e++) {
                float4 v = p[e * 32 + lane];
                float vals[4] = {v.x, v.y, v.z, v.w};
#pragma unroll
                for (int k = 0; k < 4; k++) {
                    float x = vals[k];
                    if (x > THRESH_LOGIT) {
                        unsigned mono = mono_of(x);
                        if (mono >= pivot_base) {
                            int m   = ch * CHUNK + (e * 32 + lane) * 4 + k;
                            int a   = m / CHW_;
                            int rem = m - a * CHW_;
                            int c2  = rem / HW_;
                            int hw  = rem - c2 * HW_;
                            unsigned ref_idx = (unsigned)((hw * A_ + a) * C_ + c2);
                            int pos = atomicAdd(&g_count[n], 1);
                            if (pos < CAP)
                                g_cand[n][pos] =
                                    ((unsigned long long)mono << 32) |
                                    (0xFFFFFFFFu - ref_idx);
                        }
                    }
                }
            }
        }
    }
}

// ---------------- 4: bitonic sort desc + decode top-1000 (fused) ---------
__global__ void sort_decode_kernel(const float* __restrict__ reg,
                                   const float* __restrict__ anchors) {
    extern __shared__ unsigned long long sk[];
    const int n = blockIdx.x;
    int cnt = g_count[n];
    if (cnt > CAP) cnt = CAP;
    int m = 1024;
    while (m < cnt) m <<= 1;
    for (int i = threadIdx.x; i < m; i += blockDim.x)
        sk[i] = (i < cnt) ? g_cand[n][i] : 0ULL;
    __syncthreads();
    for (int k = 2; k <= m; k <<= 1) {
        for (int j = k >> 1; j > 0; j >>= 1) {
            for (int i = threadIdx.x; i < m; i += blockDim.x) {
                int ixj = i ^ j;
                if (ixj > i) {
                    unsigned long long va = sk[i], vb = sk[ixj];
                    bool desc = ((i & k) == 0);
                    if (desc ? (va < vb) : (va > vb)) { sk[i] = vb; sk[ixj] = va; }
                }
            }
            __syncthreads();
        }
    }

    // decode (threads 0..999)
    const int r = threadIdx.x;
    bool valid = false;
    float x1 = 0.f, y1 = 0.f, x2 = 0.f, y2 = 0.f, score = -1.f;
    int label = 0;
    unsigned long long key = (r < TOPN) ? sk[r] : 0ULL;
    if (key != 0ULL) {
        unsigned mono = (unsigned)(key >> 32);
        unsigned bits = (mono & 0x80000000u) ? (mono ^ 0x80000000u) : ~mono;
        float logit = __uint_as_float(bits);
        score = 1.0f / (1.0f + expf(-logit));

        unsigned ref_idx = 0xFFFFFFFFu - (unsigned)(key & 0xFFFFFFFFull);
        int c   = (int)(ref_idx % C_);
        int loc = (int)(ref_idx / C_);
        int a   = loc % A_;
        int hw  = loc / A_;

        const float* anc = anchors + 4 * (size_t)loc;
        float ax1 = anc[0], ay1 = anc[1], ax2 = anc[2], ay2 = anc[3];
        float wdt = ax2 - ax1 + 1.0f;
        float hgt = ay2 - ay1 + 1.0f;
        float ctrx = ax1 + 0.5f * wdt;
        float ctry = ay1 + 0.5f * hgt;

        size_t rb = (size_t)n * REG_PER_IMG + (size_t)a * 4 * HW_ + hw;
        float dx = reg[rb]               / 10.0f;
        float dy = reg[rb + HW_]         / 10.0f;
        float dw = fminf(reg[rb + 2 * HW_] / 5.0f, BBOX_CLIP);
        float dh = fminf(reg[rb + 3 * HW_] / 5.0f, BBOX_CLIP);

        float pcx = dx * wdt + ctrx;
        float pcy = dy * hgt + ctry;
        float pw  = expf(dw) * wdt;
        float ph  = expf(dh) * hgt;

        x1 = pcx - 0.5f * pw;
        y1 = pcy - 0.5f * ph;
        x2 = pcx + 0.5f * pw - 1.0f;
        y2 = pcy + 0.5f * ph - 1.0f;
        x1 = fminf(fmaxf(x1, 0.0f), IMW1);
        y1 = fminf(fmaxf(y1, 0.0f), IMH1);
        x2 = fminf(fmaxf(x2, 0.0f), IMW1);
        y2 = fminf(fmaxf(y2, 0.0f), IMH1);

        valid = (score > 0.0f) &&
                (x2 - x1 + 1.0f >= 0.0f) &&
                (y2 - y1 + 1.0f >= 0.0f);
        label = c + 1;
    }
    if (r < TOPN) {
        g_boxes[n][r][0] = x1; g_boxes[n][r][1] = y1;
        g_boxes[n][r][2] = x2; g_boxes[n][r][3] = y2;
        g_scores[n][r] = score;
        g_labels[n][r] = label;
        float off = (float)label * 4096.0f;
        g_obox[n][r] = make_float4(x1 + off, y1 + off, x2 + off, y2 + off);
        g_area[n][r] = (x2 - x1 + 1.0f) * (y2 - y1 + 1.0f);
    }
    unsigned bal = __ballot_sync(FULLMASK, valid);
    if ((threadIdx.x & 31) == 0) g_validmask[n][threadIdx.x >> 5] = bal;
}

// ---------------- 5: IoU > 0.5 bitmask --------------------------------
__global__ void iou_kernel() {
    const int lane = threadIdx.x;
    const int i    = blockIdx.x * blockDim.y + threadIdx.y;
    const int word = blockIdx.y;
    const int n    = blockIdx.z;
    if (i >= TOPN) return;
    int j  = word * 32 + lane;
    int jc = (j < TOPN) ? j : (TOPN - 1);

    float4 bi = g_obox[n][i];  float ai = g_area[n][i];
    float4 bj = g_obox[n][jc]; float aj = g_area[n][jc];

    float iw = fmaxf(fminf(bi.z, bj.z) - fmaxf(bi.x, bj.x) + 1.0f, 0.0f);
    float ih = fmaxf(fminf(bi.w, bj.w) - fmaxf(bi.y, bj.y) + 1.0f, 0.0f);
    float inter = iw * ih;
    float iou = inter / (ai + aj - inter);
    bool cond = (j < TOPN) && (iou > NMS_T);
    unsigned bal = __ballot_sync(FULLMASK, cond);
    if (lane == 0) g_iou[n][i][word] = bal;
}

// ---------------- 6: serial NMS scan (1 warp/image, early exit) ----------
__global__ void nms_scan_kernel() {
    const int n = blockIdx.x;
    const int lane = threadIdx.x;           // blockDim = 32
    g_keepw[n][lane] = 0u;
    __syncwarp();

    unsigned supp = 0u;
    unsigned vmw  = g_validmask[n][lane];
    const unsigned* __restrict__ M = &g_iou[n][0][0];
    int kept = 0;
    bool early = false;

#pragma unroll 1
    for (int c = 0; c < 32; c++) {
        unsigned m[32];
#pragma unroll
        for (int j = 0; j < 32; j++) m[j] = M[(c * 32 + j) * 32 + lane];
        unsigned cur = __shfl_sync(FULLMASK, supp, c);
        unsigned vw  = __shfl_sync(FULLMASK, vmw, c);
        unsigned vals[32];
#pragma unroll
        for (int j = 0; j < 32; j++) vals[j] = __shfl_sync(FULLMASK, m[j], c);

        unsigned keepw = 0u;
#pragma unroll
        for (int j = 0; j < 32; j++) {
            unsigned ki = (vw >> j) & (~(cur >> j)) & 1u;
            keepw |= ki << j;
            unsigned msk = 0u - ki;
            cur  |= vals[j] & msk;
            supp |= m[j]    & msk;
        }
        if (lane == 0) g_keepw[n][c] = keepw;
        kept += __popc(keepw);
        if (kept >= POSTN) { early = true; break; }   // output fully determined
    }
    if (lane == 0) g_totkept[n] = early ? TOPN : kept;
}

// ---------------- 7: final top-100 emit ----------------------------------
__global__ void emit_kernel(float* __restrict__ out) {
    __shared__ int s_warpoff[32];
    __shared__ int s_tot;
    const int n = blockIdx.x;
    const int tid = threadIdx.x;
    const int lane = tid & 31, w = tid >> 5;
    const bool in = tid < TOPN;

    if (tid == 0) s_tot = g_totkept[n];
    int k = (in && ((g_keepw[n][w] >> lane) & 1u)) ? 1 : 0;
    unsigned wb = __ballot_sync(FULLMASK, k);
    int pre = __popc(wb & ((1u << lane) - 1u));
    if (lane == 0) s_warpoff[w] = __popc(wb);
    __syncthreads();
    if (tid == 0) {
        int s = 0;
        for (int x = 0; x < 32; x++) { int t2 = s_warpoff[x]; s_warpoff[x] = s; s += t2; }
    }
    __syncthreads();

    if (in) {
        int kept_before = s_warpoff[w] + pre;
        int r = k ? kept_before : (s_tot + (tid - kept_before));
        if (r < POSTN) {
            int base_b = n * POSTN * 4;
            int base_s = N_IMG * POSTN * 4 + n * POSTN;
            int base_l = N_IMG * POSTN * 5 + n * POSTN;
            out[base_b + r * 4 + 0] = g_boxes[n][tid][0];
            out[base_b + r * 4 + 1] = g_boxes[n][tid][1];
            out[base_b + r * 4 + 2] = g_boxes[n][tid][2];
            out[base_b + r * 4 + 3] = g_boxes[n][tid][3];
            out[base_s + r] = k ? g_scores[n][tid] : -1.0f;
            out[base_l + r] = k ? (float)g_labels[n][tid] : 0.0f;
        }
    }
}

// ---------------- host launch ----------------
extern "C" void kernel_launch(void* const* d_in, const int* in_sizes, int n_in,
                              void* d_out, int out_size) {
    (void)in_sizes; (void)n_in; (void)out_size;
    const float* box_cls = (const float*)d_in[0];
    const float* box_reg = (const float*)d_in[1];
    const float* anchors = (const float*)d_in[2];
    float* out = (float*)d_out;

    static bool attr_done = false;
    if (!attr_done) {
        cudaFuncSetAttribute(sort_decode_kernel,
            cudaFuncAttributeMaxDynamicSharedMemorySize, CAP * 8);
        attr_done = true;
    }

    hist_kernel<<<dim3(592, N_IMG), 256>>>(box_cls);
    pivot_kernel<<<1, 1024>>>();
    collect_kernel<<<dim3(74, N_IMG), 256>>>(box_cls);
    sort_decode_kernel<<<N_IMG, 1024, CAP * 8>>>(box_reg, anchors);
    iou_kernel<<<dim3(125, 32, N_IMG), dim3(32, 8)>>>();
    nms_scan_kernel<<<N_IMG, 32>>>();
    emit_kernel<<<N_IMG, 1024>>>(out);
}

// round 3
// speedup vs baseline: 1.3603x; 1.3603x over previous
#include <cuda_runtime.h>

// ---------------- problem constants ----------------
#define N_IMG 2
#define A_ 9
#define C_ 80
#define H_ 100
#define W_ 152
#define HW_ 15200           // H*W
#define CHW_ (C_*HW_)       // 1,216,000
#define ACHW 10944000       // A*C*H*W per image
#define REG_PER_IMG (A_*4*HW_)
#define TOPN 1000
#define POSTN 100
#define CAP 16384
#define NBINS 8192                // 13-bit buckets of mono key
#define BIN_SHIFT 19
#define CHUNK 512                 // floats per chunk
#define CPI (ACHW/CHUNK)          // 21375 chunks per image
#define NPAIRS (CPI/2)            // 10687 (CPI odd; 1 tail chunk)
#define NGROUPS ((CPI+31)/32)     // 668
#define THRESH_LOGIT -2.9444389791664403f   // log(0.05/0.95)
#define BBOX_CLIP 4.1351665567423556f       // log(1000/16)
#define IMW1 1215.0f
#define IMH1 799.0f
#define NMS_T 0.5f
#define FULLMASK 0xffffffffu

// ---------------- device scratch (static, no allocs) ----------------
__device__ unsigned            g_hist[N_IMG][NBINS];
__device__ unsigned            g_chunkmax[N_IMG][CPI];
__device__ int                 g_count[N_IMG];
__device__ int                 g_pivot[N_IMG];
__device__ unsigned long long  g_cand[N_IMG][CAP];
__device__ float               g_boxes[N_IMG][TOPN][4];
__device__ float4              g_obox[N_IMG][TOPN];
__device__ float               g_area[N_IMG][TOPN];
__device__ float               g_scores[N_IMG][TOPN];
__device__ int                 g_labels[N_IMG][TOPN];
__device__ unsigned            g_validmask[N_IMG][32];
__device__ unsigned            g_iou[N_IMG][TOPN][32];
__device__ unsigned            g_keepw[N_IMG][32];
__device__ int                 g_totkept[N_IMG];

// monotone mapping: float bits -> unsigned preserving > ordering
__device__ __forceinline__ unsigned mono_of(float x) {
    unsigned b = __float_as_uint(x);
    return b ^ ((unsigned)((int)b >> 31) | 0x80000000u);
}

// process one 512-float chunk (4 float4 per lane): hist + chunk max (mono)
__device__ __forceinline__ unsigned chunk_proc(const float4* w, unsigned* sh) {
    float mx = -3.0e38f;
#pragma unroll
    for (int e = 0; e < 4; e++) {
        float vals[4] = {w[e].x, w[e].y, w[e].z, w[e].w};
#pragma unroll
        for (int k = 0; k < 4; k++) {
            float x = vals[k];
            mx = fmaxf(mx, x);
            if (x > THRESH_LOGIT)
                atomicAdd(&sh[mono_of(x) >> BIN_SHIFT], 1u);
        }
    }
    return __reduce_max_sync(FULLMASK, mono_of(mx));
}

// ---------------- 1: histogram + per-chunk max (single DRAM sweep) --------
__global__ __launch_bounds__(256) void hist_kernel(const float* __restrict__ cls) {
    __shared__ unsigned sh[NBINS];
    for (int i = threadIdx.x; i < NBINS; i += blockDim.x) sh[i] = 0u;
    __syncthreads();
    const int n = blockIdx.y;
    const int lane = threadIdx.x & 31;
    const int gw = (blockIdx.x * blockDim.x + threadIdx.x) >> 5;
    const int nwarps = (gridDim.x * blockDim.x) >> 5;
    const float4* base = reinterpret_cast<const float4*>(cls + (size_t)n * ACHW);

    for (int pp = gw; pp < NPAIRS; pp += nwarps) {
        const float4* p = base + (size_t)pp * 256;
        float4 w[8];
#pragma unroll
        for (int e = 0; e < 8; e++) w[e] = p[e * 32 + lane];   // 8 loads in flight
        unsigned mx0 = chunk_proc(w, sh);
        unsigned mx1 = chunk_proc(w + 4, sh);
        if (lane == 0) {
            g_chunkmax[n][pp * 2 + 0] = mx0;
            g_chunkmax[n][pp * 2 + 1] = mx1;
        }
    }
    if (gw == 0) {   // tail chunk (CPI is odd)
        const float4* p = base + (size_t)(CPI - 1) * 128;
        float4 w[4];
#pragma unroll
        for (int e = 0; e < 4; e++) w[e] = p[e * 32 + lane];
        unsigned mx = chunk_proc(w, sh);
        if (lane == 0) g_chunkmax[n][CPI - 1] = mx;
    }
    __syncthreads();
    for (int i = threadIdx.x; i < NBINS; i += blockDim.x) {
        unsigned v = sh[i];
        if (v) atomicAdd(&g_hist[n][i], v);
    }
}

// ---------------- 2: find pivot bucket (256 threads, both images) ---------
__global__ __launch_bounds__(256) void pivot_kernel() {
    __shared__ unsigned ssum[256];
    const int t = threadIdx.x;
    for (int n = 0; n < N_IMG; n++) {
        // region t covers 32 bins counted from the TOP of the histogram
        const int base = NBINS - 32 * (t + 1);
        const uint4* hp = reinterpret_cast<const uint4*>(&g_hist[n][base]);
        unsigned h[32];
        uint4 v[8];
#pragma unroll
        for (int e = 0; e < 8; e++) v[e] = hp[e];
#pragma unroll
        for (int e = 0; e < 8; e++) {
            h[e * 4 + 0] = v[e].x; h[e * 4 + 1] = v[e].y;
            h[e * 4 + 2] = v[e].z; h[e * 4 + 3] = v[e].w;
        }
        unsigned s = 0;
#pragma unroll
        for (int i = 0; i < 32; i++) s += h[i];
        ssum[t] = s;
        __syncthreads();
        for (int off = 1; off < 256; off <<= 1) {
            unsigned add = (t >= off) ? ssum[t - off] : 0u;
            __syncthreads();
            ssum[t] += add;
            __syncthreads();
        }
        unsigned incl = ssum[t];
        unsigned excl = incl - s;
        if (excl < TOPN && incl >= TOPN) {     // unique crossing thread
            unsigned run = excl;
            int piv = 0;
#pragma unroll
            for (int i = 31; i >= 0; i--) {    // bins descending from top
                run += h[i];
                if (run >= TOPN) { piv = base + i; break; }
            }
            g_pivot[n] = piv;
        }
        if (t == 255 && ssum[255] < TOPN) g_pivot[n] = 0;  // fewer than TOPN total
        __syncthreads();
    }
}

// ---------------- 3: collect candidates, skipping pruned chunks ----------
__global__ __launch_bounds__(256) void collect_kernel(const float* __restrict__ cls) {
    const int n = blockIdx.y;
    const unsigned pivot_base = (unsigned)g_pivot[n] << BIN_SHIFT;
    const int lane = threadIdx.x & 31;
    const int gw = (blockIdx.x * blockDim.x + threadIdx.x) >> 5;
    const int nwarps = (gridDim.x * blockDim.x) >> 5;
    const float4* base = reinterpret_cast<const float4*>(cls + (size_t)n * ACHW);

    for (int g = gw; g < NGROUPS; g += nwarps) {
        int chbase = g * 32;
        int ch_l = chbase + lane;
        bool active = (ch_l < CPI) && (g_chunkmax[n][ch_l] >= pivot_base);
        unsigned act = __ballot_sync(FULLMASK, active);
        while (act) {
            int c = __ffs(act) - 1;
            act &= act - 1;
            int ch = chbase + c;
            const float4* p = base + (size_t)ch * 128;
#pragma unroll
            for (int e = 0; e < 4; e++) {
                float4 v = p[e * 32 + lane];
                float vals[4] = {v.x, v.y, v.z, v.w};
#pragma unroll
                for (int k = 0; k < 4; k++) {
                    float x = vals[k];
                    if (x > THRESH_LOGIT) {
                        unsigned mono = mono_of(x);
                        if (mono >= pivot_base) {
                            int m   = ch * CHUNK + (e * 32 + lane) * 4 + k;
                            int a   = m / CHW_;
                            int rem = m - a * CHW_;
                            int c2  = rem / HW_;
                            int hw  = rem - c2 * HW_;
                            unsigned ref_idx = (unsigned)((hw * A_ + a) * C_ + c2);
                            int pos = atomicAdd(&g_count[n], 1);
                            if (pos < CAP)
                                g_cand[n][pos] =
                                    ((unsigned long long)mono << 32) |
                                    (0xFFFFFFFFu - ref_idx);
                        }
                    }
                }
            }
        }
    }
}

// ---------------- 4: bitonic sort desc (hybrid barriers) + decode --------
__global__ __launch_bounds__(512) void sort_decode_kernel(
        const float* __restrict__ reg, const float* __restrict__ anchors) {
    extern __shared__ unsigned long long sk[];
    const int n = blockIdx.x;
    const int tid = threadIdx.x;
    int cnt = g_count[n];
    if (cnt > CAP) cnt = CAP;
    int m = 1024;
    while (m < cnt) m <<= 1;
    for (int i = tid; i < m; i += 512)
        sk[i] = (i < cnt) ? g_cand[n][i] : 0ULL;
    __syncthreads();
    for (int k = 2; k <= m; k <<= 1) {
        for (int j = k >> 1; j > 0; j >>= 1) {
            for (int i = tid; i < m; i += 512) {
                int ixj = i ^ j;
                if (ixj > i) {
                    unsigned long long va = sk[i], vb = sk[ixj];
                    bool desc = ((i & k) == 0);
                    if (desc ? (va < vb) : (va > vb)) { sk[i] = vb; sk[ixj] = va; }
                }
            }
            // distance-j exchange is warp-local when j<32 (threads strided by 512)
            if (j > 1 && j < 32) __syncwarp();
            else                 __syncthreads();
        }
    }

    // decode: threads handle r = tid and tid+512
#pragma unroll
    for (int it = 0; it < 2; it++) {
        const int r = tid + it * 512;
        bool valid = false;
        float x1 = 0.f, y1 = 0.f, x2 = 0.f, y2 = 0.f, score = -1.f;
        int label = 0;
        unsigned long long key = (r < TOPN) ? sk[r] : 0ULL;
        if (key != 0ULL) {
            unsigned mono = (unsigned)(key >> 32);
            unsigned bits = (mono & 0x80000000u) ? (mono ^ 0x80000000u) : ~mono;
            float logit = __uint_as_float(bits);
            score = 1.0f / (1.0f + expf(-logit));

            unsigned ref_idx = 0xFFFFFFFFu - (unsigned)(key & 0xFFFFFFFFull);
            int c   = (int)(ref_idx % C_);
            int loc = (int)(ref_idx / C_);
            int a   = loc % A_;
            int hw  = loc / A_;

            const float* anc = anchors + 4 * (size_t)loc;
            float ax1 = anc[0], ay1 = anc[1], ax2 = anc[2], ay2 = anc[3];
            float wdt = ax2 - ax1 + 1.0f;
            float hgt = ay2 - ay1 + 1.0f;
            float ctrx = ax1 + 0.5f * wdt;
            float ctry = ay1 + 0.5f * hgt;

            size_t rb = (size_t)n * REG_PER_IMG + (size_t)a * 4 * HW_ + hw;
            float dx = reg[rb]               / 10.0f;
            float dy = reg[rb + HW_]         / 10.0f;
            float dw = fminf(reg[rb + 2 * HW_] / 5.0f, BBOX_CLIP);
            float dh = fminf(reg[rb + 3 * HW_] / 5.0f, BBOX_CLIP);

            float pcx = dx * wdt + ctrx;
            float pcy = dy * hgt + ctry;
            float pw  = expf(dw) * wdt;
            float ph  = expf(dh) * hgt;

            x1 = pcx - 0.5f * pw;
            y1 = pcy - 0.5f * ph;
            x2 = pcx + 0.5f * pw - 1.0f;
            y2 = pcy + 0.5f * ph - 1.0f;
            x1 = fminf(fmaxf(x1, 0.0f), IMW1);
            y1 = fminf(fmaxf(y1, 0.0f), IMH1);
            x2 = fminf(fmaxf(x2, 0.0f), IMW1);
            y2 = fminf(fmaxf(y2, 0.0f), IMH1);

            valid = (score > 0.0f) &&
                    (x2 - x1 + 1.0f >= 0.0f) &&
                    (y2 - y1 + 1.0f >= 0.0f);
            label = c + 1;
        }
        if (r < TOPN) {
            g_boxes[n][r][0] = x1; g_boxes[n][r][1] = y1;
            g_boxes[n][r][2] = x2; g_boxes[n][r][3] = y2;
            g_scores[n][r] = score;
            g_labels[n][r] = label;
            float off = (float)label * 4096.0f;
            g_obox[n][r] = make_float4(x1 + off, y1 + off, x2 + off, y2 + off);
            g_area[n][r] = (x2 - x1 + 1.0f) * (y2 - y1 + 1.0f);
        }
        unsigned bal = __ballot_sync(FULLMASK, valid);
        int word = r >> 5;
        if ((tid & 31) == 0 && word < 32) g_validmask[n][word] = bal;
    }
}

// ---------------- 5: IoU > 0.5 bitmask --------------------------------
__global__ void iou_kernel() {
    const int lane = threadIdx.x;
    const int i    = blockIdx.x * blockDim.y + threadIdx.y;
    const int word = blockIdx.y;
    const int n    = blockIdx.z;
    if (i >= TOPN) return;
    int j  = word * 32 + lane;
    int jc = (j < TOPN) ? j : (TOPN - 1);

    float4 bi = g_obox[n][i];  float ai = g_area[n][i];
    float4 bj = g_obox[n][jc]; float aj = g_area[n][jc];

    float iw = fmaxf(fminf(bi.z, bj.z) - fmaxf(bi.x, bj.x) + 1.0f, 0.0f);
    float ih = fmaxf(fminf(bi.w, bj.w) - fmaxf(bi.y, bj.y) + 1.0f, 0.0f);
    float inter = iw * ih;
    float iou = inter / (ai + aj - inter);
    bool cond = (j < TOPN) && (iou > NMS_T);
    unsigned bal = __ballot_sync(FULLMASK, cond);
    if (lane == 0) g_iou[n][i][word] = bal;
}

// ---------------- 6: serial NMS scan (1 warp/image, prefetch+early-exit) --
__global__ void nms_scan_kernel() {
    const int n = blockIdx.x;
    const int lane = threadIdx.x;           // blockDim = 32
    g_keepw[n][lane] = 0u;
    __syncwarp();

    unsigned supp = 0u;
    unsigned vmw  = g_validmask[n][lane];
    const unsigned* __restrict__ M = &g_iou[n][0][0];
    int kept = 0;
    bool early = false;

    unsigned mN[32];
#pragma unroll
    for (int j = 0; j < 32; j++) mN[j] = M[j * 32 + lane];   // prefetch chunk 0

#pragma unroll 1
    for (int c = 0; c < 32; c++) {
        unsigned m[32];
#pragma unroll
        for (int j = 0; j < 32; j++) m[j] = mN[j];
        if (c < 31) {                                         // prefetch next chunk
#pragma unroll
            for (int j = 0; j < 32; j++) mN[j] = M[((c + 1) * 32 + j) * 32 + lane];
        }
        unsigned cur = __shfl_sync(FULLMASK, supp, c);
        unsigned vw  = __shfl_sync(FULLMASK, vmw, c);
        unsigned vals[32];
#pragma unroll
        for (int j = 0; j < 32; j++) vals[j] = __shfl_sync(FULLMASK, m[j], c);

        unsigned keepw = 0u;
#pragma unroll
        for (int j = 0; j < 32; j++) {
            unsigned ki = (vw >> j) & (~(cur >> j)) & 1u;
            keepw |= ki << j;
            unsigned msk = 0u - ki;
            cur  |= vals[j] & msk;
            supp |= m[j]    & msk;
        }
        if (lane == 0) g_keepw[n][c] = keepw;
        kept += __popc(keepw);
        if (kept >= POSTN) { early = true; break; }   // output fully determined
    }
    if (lane == 0) g_totkept[n] = early ? TOPN : kept;
}

// ---------------- 7: final top-100 emit + state reset ---------------------
__global__ void emit_kernel(float* __restrict__ out) {
    __shared__ int s_warpoff[32];
    __shared__ int s_tot;
    const int n = blockIdx.x;
    const int tid = threadIdx.x;
    const int lane = tid & 31, w = tid >> 5;
    const bool in = tid < TOPN;

    if (tid == 0) s_tot = g_totkept[n];
    int k = (in && ((g_keepw[n][w] >> lane) & 1u)) ? 1 : 0;
    unsigned wb = __ballot_sync(FULLMASK, k);
    int pre = __popc(wb & ((1u << lane) - 1u));
    if (lane == 0) s_warpoff[w] = __popc(wb);
    __syncthreads();
    if (tid == 0) {
        int s = 0;
        for (int x = 0; x < 32; x++) { int t2 = s_warpoff[x]; s_warpoff[x] = s; s += t2; }
    }
    __syncthreads();

    if (in) {
        int kept_before = s_warpoff[w] + pre;
        int r = k ? kept_before : (s_tot + (tid - kept_before));
        if (r < POSTN) {
            int base_b = n * POSTN * 4;
            int base_s = N_IMG * POSTN * 4 + n * POSTN;
            int base_l = N_IMG * POSTN * 5 + n * POSTN;
            out[base_b + r * 4 + 0] = g_boxes[n][tid][0];
            out[base_b + r * 4 + 1] = g_boxes[n][tid][1];
            out[base_b + r * 4 + 2] = g_boxes[n][tid][2];
            out[base_b + r * 4 + 3] = g_boxes[n][tid][3];
            out[base_s + r] = k ? g_scores[n][tid] : -1.0f;
            out[base_l + r] = k ? (float)g_labels[n][tid] : 0.0f;
        }
    }

    // reset per-replay state for the next graph replay
    for (int i = tid; i < NBINS; i += 1024) g_hist[n][i] = 0u;
    if (tid == 0) g_count[n] = 0;
}

// ---------------- host launch ----------------
extern "C" void kernel_launch(void* const* d_in, const int* in_sizes, int n_in,
                              void* d_out, int out_size) {
    (void)in_sizes; (void)n_in; (void)out_size;
    const float* box_cls = (const float*)d_in[0];
    const float* box_reg = (const float*)d_in[1];
    const float* anchors = (const float*)d_in[2];
    float* out = (float*)d_out;

    static bool attr_done = false;
    if (!attr_done) {
        cudaFuncSetAttribute(sort_decode_kernel,
            cudaFuncAttributeMaxDynamicSharedMemorySize, CAP * 8);
        attr_done = true;
    }

    hist_kernel<<<dim3(592, N_IMG), 256>>>(box_cls);
    pivot_kernel<<<1, 256>>>();
    collect_kernel<<<dim3(74, N_IMG), 256>>>(box_cls);
    sort_decode_kernel<<<N_IMG, 512, CAP * 8>>>(box_reg, anchors);
    iou_kernel<<<dim3(125, 32, N_IMG), dim3(32, 8)>>>();
    nms_scan_kernel<<<N_IMG, 32>>>();
    emit_kernel<<<N_IMG, 1024>>>(out);
}

// round 4
// speedup vs baseline: 1.7433x; 1.2815x over previous
#include <cuda_runtime.h>

// ---------------- problem constants ----------------
#define N_IMG 2
#define A_ 9
#define C_ 80
#define H_ 100
#define W_ 152
#define HW_ 15200           // H*W
#define CHW_ (C_*HW_)       // 1,216,000
#define ACHW 10944000       // A*C*H*W per image
#define REG_PER_IMG (A_*4*HW_)
#define TOPN 1000
#define POSTN 100
#define CAP 16384
#define NBINS 8192                // 13-bit buckets of mono key
#define BIN_SHIFT 19
#define CHUNK 512                 // floats per chunk
#define CPI (ACHW/CHUNK)          // 21375 chunks per image
#define NQUADS (CPI/4)            // 5343 quads (4 chunks each)
#define QTAIL (CPI - 4*NQUADS)    // 3 tail chunks
#define NGROUPS ((CPI+31)/32)     // 668
#define THRESH_LOGIT -2.9444389791664403f   // log(0.05/0.95)
#define BBOX_CLIP 4.1351665567423556f       // log(1000/16)
#define IMW1 1215.0f
#define IMH1 799.0f
#define NMS_T 0.5f
#define FULLMASK 0xffffffffu
#define RANK_BLK 128
#define RANK_GRID ((CAP + RANK_BLK - 1) / RANK_BLK)   // 128 blocks/img

// ---------------- device scratch (static, no allocs) ----------------
__device__ unsigned            g_hist[N_IMG][NBINS];
__device__ unsigned            g_chunkmax[N_IMG][CPI];
__device__ int                 g_count[N_IMG];
__device__ int                 g_pivot[N_IMG];
__device__ unsigned long long  g_cand[N_IMG][CAP];
__device__ float               g_boxes[N_IMG][TOPN][4];
__device__ float4              g_obox[N_IMG][TOPN];
__device__ float               g_area[N_IMG][TOPN];
__device__ float               g_scores[N_IMG][TOPN];
__device__ int                 g_labels[N_IMG][TOPN];
__device__ unsigned            g_validmask[N_IMG][32];
__device__ unsigned            g_iou[N_IMG][TOPN][32];
__device__ unsigned            g_keepw[N_IMG][32];
__device__ int                 g_totkept[N_IMG];

// monotone mapping: float bits -> unsigned preserving > ordering
__device__ __forceinline__ unsigned mono_of(float x) {
    unsigned b = __float_as_uint(x);
    return b ^ ((unsigned)((int)b >> 31) | 0x80000000u);
}

// process one 512-float chunk (4 float4 per lane): hist + chunk max (mono)
__device__ __forceinline__ unsigned chunk_proc(const float4* w, unsigned* sh) {
    float mx = -3.0e38f;
#pragma unroll
    for (int e = 0; e < 4; e++) {
        float vals[4] = {w[e].x, w[e].y, w[e].z, w[e].w};
#pragma unroll
        for (int k = 0; k < 4; k++) {
            float x = vals[k];
            mx = fmaxf(mx, x);
            if (x > THRESH_LOGIT)
                atomicAdd(&sh[mono_of(x) >> BIN_SHIFT], 1u);
        }
    }
    return __reduce_max_sync(FULLMASK, mono_of(mx));
}

// ---------------- 1: histogram + per-chunk max (single DRAM sweep) --------
__global__ __launch_bounds__(256) void hist_kernel(const float* __restrict__ cls) {
    __shared__ unsigned sh[NBINS];
    for (int i = threadIdx.x; i < NBINS; i += blockDim.x) sh[i] = 0u;
    __syncthreads();
    const int n = blockIdx.y;
    const int lane = threadIdx.x & 31;
    const int gw = (blockIdx.x * blockDim.x + threadIdx.x) >> 5;
    const int nwarps = (gridDim.x * blockDim.x) >> 5;
    const float4* base = reinterpret_cast<const float4*>(cls + (size_t)n * ACHW);

    for (int q = gw; q < NQUADS; q += nwarps) {
        const float4* p = base + (size_t)q * 512;
        float4 w[16];
#pragma unroll
        for (int e = 0; e < 16; e++) w[e] = p[e * 32 + lane];  // 16 loads in flight
        unsigned mx0 = chunk_proc(w,      sh);
        unsigned mx1 = chunk_proc(w + 4,  sh);
        unsigned mx2 = chunk_proc(w + 8,  sh);
        unsigned mx3 = chunk_proc(w + 12, sh);
        if (lane == 0) {
            g_chunkmax[n][q * 4 + 0] = mx0;
            g_chunkmax[n][q * 4 + 1] = mx1;
            g_chunkmax[n][q * 4 + 2] = mx2;
            g_chunkmax[n][q * 4 + 3] = mx3;
        }
    }
    if (gw == 0) {   // 3 tail chunks
        const float4* p = base + (size_t)(NQUADS * 4) * 128;
        float4 w[12];
#pragma unroll
        for (int e = 0; e < 12; e++) w[e] = p[e * 32 + lane];
        unsigned mx0 = chunk_proc(w,     sh);
        unsigned mx1 = chunk_proc(w + 4, sh);
        unsigned mx2 = chunk_proc(w + 8, sh);
        if (lane == 0) {
            g_chunkmax[n][NQUADS * 4 + 0] = mx0;
            g_chunkmax[n][NQUADS * 4 + 1] = mx1;
            g_chunkmax[n][NQUADS * 4 + 2] = mx2;
        }
    }
    __syncthreads();
    for (int i = threadIdx.x; i < NBINS; i += blockDim.x) {
        unsigned v = sh[i];
        if (v) atomicAdd(&g_hist[n][i], v);
    }
}

// ---------------- 2: find pivot bucket (256 threads, both images) ---------
__global__ __launch_bounds__(256) void pivot_kernel() {
    __shared__ unsigned ssum[256];
    const int t = threadIdx.x;
    for (int n = 0; n < N_IMG; n++) {
        const int base = NBINS - 32 * (t + 1);
        const uint4* hp = reinterpret_cast<const uint4*>(&g_hist[n][base]);
        unsigned h[32];
        uint4 v[8];
#pragma unroll
        for (int e = 0; e < 8; e++) v[e] = hp[e];
#pragma unroll
        for (int e = 0; e < 8; e++) {
            h[e * 4 + 0] = v[e].x; h[e * 4 + 1] = v[e].y;
            h[e * 4 + 2] = v[e].z; h[e * 4 + 3] = v[e].w;
        }
        unsigned s = 0;
#pragma unroll
        for (int i = 0; i < 32; i++) s += h[i];
        ssum[t] = s;
        __syncthreads();
        for (int off = 1; off < 256; off <<= 1) {
            unsigned add = (t >= off) ? ssum[t - off] : 0u;
            __syncthreads();
            ssum[t] += add;
            __syncthreads();
        }
        unsigned incl = ssum[t];
        unsigned excl = incl - s;
        if (excl < TOPN && incl >= TOPN) {
            unsigned run = excl;
            int piv = 0;
#pragma unroll
            for (int i = 31; i >= 0; i--) {
                run += h[i];
                if (run >= TOPN) { piv = base + i; break; }
            }
            g_pivot[n] = piv;
        }
        if (t == 255 && ssum[255] < TOPN) g_pivot[n] = 0;
        __syncthreads();
    }
}

// ---------------- 3: collect candidates, skipping pruned chunks ----------
__global__ __launch_bounds__(256) void collect_kernel(const float* __restrict__ cls) {
    const int n = blockIdx.y;
    const unsigned pivot_base = (unsigned)g_pivot[n] << BIN_SHIFT;
    const int lane = threadIdx.x & 31;
    const int gw = (blockIdx.x * blockDim.x + threadIdx.x) >> 5;
    const int nwarps = (gridDim.x * blockDim.x) >> 5;
    const float4* base = reinterpret_cast<const float4*>(cls + (size_t)n * ACHW);

    for (int g = gw; g < NGROUPS; g += nwarps) {
        int chbase = g * 32;
        int ch_l = chbase + lane;
        bool active = (ch_l < CPI) && (g_chunkmax[n][ch_l] >= pivot_base);
        unsigned act = __ballot_sync(FULLMASK, active);
        while (act) {
            int c = __ffs(act) - 1;
            act &= act - 1;
            int ch = chbase + c;
            const float4* p = base + (size_t)ch * 128;
#pragma unroll
            for (int e = 0; e < 4; e++) {
                float4 v = p[e * 32 + lane];
                float vals[4] = {v.x, v.y, v.z, v.w};
#pragma unroll
                for (int k = 0; k < 4; k++) {
                    float x = vals[k];
                    if (x > THRESH_LOGIT) {
                        unsigned mono = mono_of(x);
                        if (mono >= pivot_base) {
                            int m   = ch * CHUNK + (e * 32 + lane) * 4 + k;
                            int a   = m / CHW_;
                            int rem = m - a * CHW_;
                            int c2  = rem / HW_;
                            int hw  = rem - c2 * HW_;
                            unsigned ref_idx = (unsigned)((hw * A_ + a) * C_ + c2);
                            int pos = atomicAdd(&g_count[n], 1);
                            if (pos < CAP)
                                g_cand[n][pos] =
                                    ((unsigned long long)mono << 32) |
                                    (0xFFFFFFFFu - ref_idx);
                        }
                    }
                }
            }
        }
    }
}

// ------- 4: enumeration-sort rank + decode + scatter (no bitonic) ---------
// rank_i = #{j : key_j > key_i}; keys are unique, so ranks are a bijection.
__global__ __launch_bounds__(RANK_BLK) void rank_decode_kernel(
        const float* __restrict__ reg, const float* __restrict__ anchors) {
    extern __shared__ unsigned long long sk[];
    const int n = blockIdx.y;
    int cnt = g_count[n];
    if (cnt > CAP) cnt = CAP;
    const int idx = blockIdx.x * RANK_BLK + threadIdx.x;
    const int blk_lo = blockIdx.x * RANK_BLK;
    if (blk_lo >= cnt && blk_lo >= TOPN) return;   // nothing to rank or fill

    // default fill for slots [cnt, TOPN) when cnt < TOPN
    if (idx >= cnt) {
        if (idx < TOPN) {
            g_boxes[n][idx][0] = 0.f; g_boxes[n][idx][1] = 0.f;
            g_boxes[n][idx][2] = 0.f; g_boxes[n][idx][3] = 0.f;
            g_scores[n][idx] = -1.0f;
            g_labels[n][idx] = 0;
            g_obox[n][idx] = make_float4(0.f, 0.f, 0.f, 0.f);
            g_area[n][idx] = 1.0f;
        }
        if (blk_lo >= cnt) return;   // whole block is fill-only -> skip load
    }

    for (int i = threadIdx.x; i < cnt; i += RANK_BLK)
        sk[i] = g_cand[n][i];
    __syncthreads();

    if (idx >= cnt) return;
    const unsigned long long mykey = sk[idx];
    int r0 = 0, r1 = 0, r2 = 0, r3 = 0;
    int j = 0;
    for (; j + 4 <= cnt; j += 4) {
        r0 += (sk[j + 0] > mykey);
        r1 += (sk[j + 1] > mykey);
        r2 += (sk[j + 2] > mykey);
        r3 += (sk[j + 3] > mykey);
    }
    for (; j < cnt; j++) r0 += (sk[j] > mykey);
    const int rank = r0 + r1 + r2 + r3;
    if (rank >= TOPN) return;

    // decode
    unsigned mono = (unsigned)(mykey >> 32);
    unsigned bits = (mono & 0x80000000u) ? (mono ^ 0x80000000u) : ~mono;
    float logit = __uint_as_float(bits);
    float score = 1.0f / (1.0f + expf(-logit));

    unsigned ref_idx = 0xFFFFFFFFu - (unsigned)(mykey & 0xFFFFFFFFull);
    int c   = (int)(ref_idx % C_);
    int loc = (int)(ref_idx / C_);
    int a   = loc % A_;
    int hw  = loc / A_;

    const float* anc = anchors + 4 * (size_t)loc;
    float ax1 = anc[0], ay1 = anc[1], ax2 = anc[2], ay2 = anc[3];
    float wdt = ax2 - ax1 + 1.0f;
    float hgt = ay2 - ay1 + 1.0f;
    float ctrx = ax1 + 0.5f * wdt;
    float ctry = ay1 + 0.5f * hgt;

    size_t rb = (size_t)n * REG_PER_IMG + (size_t)a * 4 * HW_ + hw;
    float dx = reg[rb]               / 10.0f;
    float dy = reg[rb + HW_]         / 10.0f;
    float dw = fminf(reg[rb + 2 * HW_] / 5.0f, BBOX_CLIP);
    float dh = fminf(reg[rb + 3 * HW_] / 5.0f, BBOX_CLIP);

    float pcx = dx * wdt + ctrx;
    float pcy = dy * hgt + ctry;
    float pw  = expf(dw) * wdt;
    float ph  = expf(dh) * hgt;

    float x1 = pcx - 0.5f * pw;
    float y1 = pcy - 0.5f * ph;
    float x2 = pcx + 0.5f * pw - 1.0f;
    float y2 = pcy + 0.5f * ph - 1.0f;
    x1 = fminf(fmaxf(x1, 0.0f), IMW1);
    y1 = fminf(fmaxf(y1, 0.0f), IMH1);
    x2 = fminf(fmaxf(x2, 0.0f), IMW1);
    y2 = fminf(fmaxf(y2, 0.0f), IMH1);

    bool valid = (score > 0.0f) &&
                 (x2 - x1 + 1.0f >= 0.0f) &&
                 (y2 - y1 + 1.0f >= 0.0f);
    int label = c + 1;

    g_boxes[n][rank][0] = x1; g_boxes[n][rank][1] = y1;
    g_boxes[n][rank][2] = x2; g_boxes[n][rank][3] = y2;
    g_scores[n][rank] = score;
    g_labels[n][rank] = label;
    float off = (float)label * 4096.0f;
    g_obox[n][rank] = make_float4(x1 + off, y1 + off, x2 + off, y2 + off);
    g_area[n][rank] = (x2 - x1 + 1.0f) * (y2 - y1 + 1.0f);
    if (valid) atomicOr(&g_validmask[n][rank >> 5], 1u << (rank & 31));
}

// ---------------- 5: IoU > 0.5 bitmask --------------------------------
__global__ void iou_kernel() {
    const int lane = threadIdx.x;
    const int i    = blockIdx.x * blockDim.y + threadIdx.y;
    const int word = blockIdx.y;
    const int n    = blockIdx.z;
    if (i >= TOPN) return;
    int j  = word * 32 + lane;
    int jc = (j < TOPN) ? j : (TOPN - 1);

    float4 bi = g_obox[n][i];  float ai = g_area[n][i];
    float4 bj = g_obox[n][jc]; float aj = g_area[n][jc];

    float iw = fmaxf(fminf(bi.z, bj.z) - fmaxf(bi.x, bj.x) + 1.0f, 0.0f);
    float ih = fmaxf(fminf(bi.w, bj.w) - fmaxf(bi.y, bj.y) + 1.0f, 0.0f);
    float inter = iw * ih;
    float iou = inter / (ai + aj - inter);
    bool cond = (j < TOPN) && (iou > NMS_T);
    unsigned bal = __ballot_sync(FULLMASK, cond);
    if (lane == 0) g_iou[n][i][word] = bal;
}

// ---------------- 6: serial NMS scan (1 warp/image, prefetch+early-exit) --
__global__ void nms_scan_kernel() {
    const int n = blockIdx.x;
    const int lane = threadIdx.x;           // blockDim = 32
    g_keepw[n][lane] = 0u;
    __syncwarp();

    unsigned supp = 0u;
    unsigned vmw  = g_validmask[n][lane];
    const unsigned* __restrict__ M = &g_iou[n][0][0];
    int kept = 0;
    bool early = false;

    unsigned mN[32];
#pragma unroll
    for (int j = 0; j < 32; j++) mN[j] = M[j * 32 + lane];   // prefetch chunk 0

#pragma unroll 1
    for (int c = 0; c < 32; c++) {
        unsigned m[32];
#pragma unroll
        for (int j = 0; j < 32; j++) m[j] = mN[j];
        if (c < 31) {
#pragma unroll
            for (int j = 0; j < 32; j++) mN[j] = M[((c + 1) * 32 + j) * 32 + lane];
        }
        unsigned cur = __shfl_sync(FULLMASK, supp, c);
        unsigned vw  = __shfl_sync(FULLMASK, vmw, c);
        unsigned vals[32];
#pragma unroll
        for (int j = 0; j < 32; j++) vals[j] = __shfl_sync(FULLMASK, m[j], c);

        unsigned keepw = 0u;
#pragma unroll
        for (int j = 0; j < 32; j++) {
            unsigned ki = (vw >> j) & (~(cur >> j)) & 1u;
            keepw |= ki << j;
            unsigned msk = 0u - ki;
            cur  |= vals[j] & msk;
            supp |= m[j]    & msk;
        }
        if (lane == 0) g_keepw[n][c] = keepw;
        kept += __popc(keepw);
        if (kept >= POSTN) { early = true; break; }
    }
    if (lane == 0) g_totkept[n] = early ? TOPN : kept;
}

// ---------------- 7: final top-100 emit + state reset ---------------------
__global__ void emit_kernel(float* __restrict__ out) {
    __shared__ int s_warpoff[32];
    __shared__ int s_tot;
    const int n = blockIdx.x;
    const int tid = threadIdx.x;
    const int lane = tid & 31, w = tid >> 5;
    const bool in = tid < TOPN;

    if (tid == 0) s_tot = g_totkept[n];
    int k = (in && ((g_keepw[n][w] >> lane) & 1u)) ? 1 : 0;
    unsigned wb = __ballot_sync(FULLMASK, k);
    int pre = __popc(wb & ((1u << lane) - 1u));
    if (lane == 0) s_warpoff[w] = __popc(wb);
    __syncthreads();
    if (tid == 0) {
        int s = 0;
        for (int x = 0; x < 32; x++) { int t2 = s_warpoff[x]; s_warpoff[x] = s; s += t2; }
    }
    __syncthreads();

    if (in) {
        int kept_before = s_warpoff[w] + pre;
        int r = k ? kept_before : (s_tot + (tid - kept_before));
        if (r < POSTN) {
            int base_b = n * POSTN * 4;
            int base_s = N_IMG * POSTN * 4 + n * POSTN;
            int base_l = N_IMG * POSTN * 5 + n * POSTN;
            out[base_b + r * 4 + 0] = g_boxes[n][tid][0];
            out[base_b + r * 4 + 1] = g_boxes[n][tid][1];
            out[base_b + r * 4 + 2] = g_boxes[n][tid][2];
            out[base_b + r * 4 + 3] = g_boxes[n][tid][3];
            out[base_s + r] = k ? g_scores[n][tid] : -1.0f;
            out[base_l + r] = k ? (float)g_labels[n][tid] : 0.0f;
        }
    }

    // reset per-replay state for the next graph replay
    for (int i = tid; i < NBINS; i += 1024) g_hist[n][i] = 0u;
    if (tid < 32) g_validmask[n][tid] = 0u;
    if (tid == 0) g_count[n] = 0;
}

// ---------------- host launch ----------------
extern "C" void kernel_launch(void* const* d_in, const int* in_sizes, int n_in,
                              void* d_out, int out_size) {
    (void)in_sizes; (void)n_in; (void)out_size;
    const float* box_cls = (const float*)d_in[0];
    const float* box_reg = (const float*)d_in[1];
    const float* anchors = (const float*)d_in[2];
    float* out = (float*)d_out;

    static bool attr_done = false;
    if (!attr_done) {
        cudaFuncSetAttribute(rank_decode_kernel,
            cudaFuncAttributeMaxDynamicSharedMemorySize, CAP * 8);
        attr_done = true;
    }

    hist_kernel<<<dim3(334, N_IMG), 256>>>(box_cls);
    pivot_kernel<<<1, 256>>>();
    collect_kernel<<<dim3(74, N_IMG), 256>>>(box_cls);
    rank_decode_kernel<<<dim3(RANK_GRID, N_IMG), RANK_BLK, CAP * 8>>>(box_reg, anchors);
    iou_kernel<<<dim3(125, 32, N_IMG), dim3(32, 8)>>>();
    nms_scan_kernel<<<N_IMG, 32>>>();
    emit_kernel<<<N_IMG, 1024>>>(out);
}

// round 5
// speedup vs baseline: 1.8375x; 1.0540x over previous
#include <cuda_runtime.h>

// ---------------- problem constants ----------------
#define N_IMG 2
#define A_ 9
#define C_ 80
#define H_ 100
#define W_ 152
#define HW_ 15200           // H*W
#define CHW_ (C_*HW_)       // 1,216,000
#define ACHW 10944000       // A*C*H*W per image
#define REG_PER_IMG (A_*4*HW_)
#define TOPN 1000
#define POSTN 100
#define SCAP 4096                 // candidate cap (expected cnt ~1100)
#define NBINS 8192                // 13-bit buckets of mono key
#define BIN_SHIFT 19
#define CHUNK 512                 // floats per chunk
#define CPI (ACHW/CHUNK)          // 21375 chunks per image
#define NQUADS (CPI/4)            // 5343 quads (4 chunks each)
#define NGROUPS ((CPI+31)/32)     // 668
#define THRESH_LOGIT -2.9444389791664403f   // log(0.05/0.95)
#define BBOX_CLIP 4.1351665567423556f       // log(1000/16)
#define IMW1 1215.0f
#define IMH1 799.0f
#define NMS_T 0.5f
#define FULLMASK 0xffffffffu
#define CAND_PER_BLK 16           // 128 threads, 8 threads per candidate
#define RANK_GRID (SCAP / CAND_PER_BLK)   // 256 blocks per image

// ---------------- device scratch (static, no allocs) ----------------
__device__ unsigned            g_hist[N_IMG][NBINS];
__device__ unsigned            g_chunkmax[N_IMG][CPI];
__device__ int                 g_count[N_IMG];
__device__ int                 g_pivot[N_IMG];
__device__ unsigned long long  g_cand[N_IMG][SCAP];
__device__ float               g_boxes[N_IMG][TOPN][4];
__device__ float4              g_obox[N_IMG][TOPN];
__device__ float               g_area[N_IMG][TOPN];
__device__ float               g_scores[N_IMG][TOPN];
__device__ int                 g_labels[N_IMG][TOPN];
__device__ unsigned            g_validmask[N_IMG][32];
__device__ unsigned            g_iou[N_IMG][TOPN][32];

// monotone mapping: float bits -> unsigned preserving > ordering
__device__ __forceinline__ unsigned mono_of(float x) {
    unsigned b = __float_as_uint(x);
    return b ^ ((unsigned)((int)b >> 31) | 0x80000000u);
}

// process one 512-float chunk (4 float4 per lane): hist + chunk max (mono)
__device__ __forceinline__ unsigned chunk_proc(const float4* w, unsigned* sh) {
    float mx = -3.0e38f;
#pragma unroll
    for (int e = 0; e < 4; e++) {
        float vals[4] = {w[e].x, w[e].y, w[e].z, w[e].w};
#pragma unroll
        for (int k = 0; k < 4; k++) {
            float x = vals[k];
            mx = fmaxf(mx, x);
            if (x > THRESH_LOGIT)
                atomicAdd(&sh[mono_of(x) >> BIN_SHIFT], 1u);
        }
    }
    return __reduce_max_sync(FULLMASK, mono_of(mx));
}

// ---------------- 1: histogram + per-chunk max (single DRAM sweep) --------
__global__ __launch_bounds__(256) void hist_kernel(const float* __restrict__ cls) {
    __shared__ unsigned sh[NBINS];
    for (int i = threadIdx.x; i < NBINS; i += blockDim.x) sh[i] = 0u;
    __syncthreads();
    const int n = blockIdx.y;
    const int lane = threadIdx.x & 31;
    const int gw = (blockIdx.x * blockDim.x + threadIdx.x) >> 5;
    const int nwarps = (gridDim.x * blockDim.x) >> 5;
    const float4* base = reinterpret_cast<const float4*>(cls + (size_t)n * ACHW);

    for (int q = gw; q < NQUADS; q += nwarps) {
        const float4* p = base + (size_t)q * 512;
        float4 w[16];
#pragma unroll
        for (int e = 0; e < 16; e++) w[e] = p[e * 32 + lane];  // 16 loads in flight
        unsigned mx0 = chunk_proc(w,      sh);
        unsigned mx1 = chunk_proc(w + 4,  sh);
        unsigned mx2 = chunk_proc(w + 8,  sh);
        unsigned mx3 = chunk_proc(w + 12, sh);
        if (lane == 0) {
            g_chunkmax[n][q * 4 + 0] = mx0;
            g_chunkmax[n][q * 4 + 1] = mx1;
            g_chunkmax[n][q * 4 + 2] = mx2;
            g_chunkmax[n][q * 4 + 3] = mx3;
        }
    }
    if (gw == 0) {   // 3 tail chunks
        const float4* p = base + (size_t)(NQUADS * 4) * 128;
        float4 w[12];
#pragma unroll
        for (int e = 0; e < 12; e++) w[e] = p[e * 32 + lane];
        unsigned mx0 = chunk_proc(w,     sh);
        unsigned mx1 = chunk_proc(w + 4, sh);
        unsigned mx2 = chunk_proc(w + 8, sh);
        if (lane == 0) {
            g_chunkmax[n][NQUADS * 4 + 0] = mx0;
            g_chunkmax[n][NQUADS * 4 + 1] = mx1;
            g_chunkmax[n][NQUADS * 4 + 2] = mx2;
        }
    }
    __syncthreads();
    for (int i = threadIdx.x; i < NBINS; i += blockDim.x) {
        unsigned v = sh[i];
        if (v) atomicAdd(&g_hist[n][i], v);
    }
}

// ---------------- 2: find pivot bucket (256 threads, both images) ---------
__global__ __launch_bounds__(256) void pivot_kernel() {
    __shared__ unsigned ssum[256];
    const int t = threadIdx.x;
    for (int n = 0; n < N_IMG; n++) {
        const int base = NBINS - 32 * (t + 1);
        const uint4* hp = reinterpret_cast<const uint4*>(&g_hist[n][base]);
        unsigned h[32];
        uint4 v[8];
#pragma unroll
        for (int e = 0; e < 8; e++) v[e] = hp[e];
#pragma unroll
        for (int e = 0; e < 8; e++) {
            h[e * 4 + 0] = v[e].x; h[e * 4 + 1] = v[e].y;
            h[e * 4 + 2] = v[e].z; h[e * 4 + 3] = v[e].w;
        }
        unsigned s = 0;
#pragma unroll
        for (int i = 0; i < 32; i++) s += h[i];
        ssum[t] = s;
        __syncthreads();
        for (int off = 1; off < 256; off <<= 1) {
            unsigned add = (t >= off) ? ssum[t - off] : 0u;
            __syncthreads();
            ssum[t] += add;
            __syncthreads();
        }
        unsigned incl = ssum[t];
        unsigned excl = incl - s;
        if (excl < TOPN && incl >= TOPN) {
            unsigned run = excl;
            int piv = 0;
#pragma unroll
            for (int i = 31; i >= 0; i--) {
                run += h[i];
                if (run >= TOPN) { piv = base + i; break; }
            }
            g_pivot[n] = piv;
        }
        if (t == 255 && ssum[255] < TOPN) g_pivot[n] = 0;
        __syncthreads();
    }
}

// ---------------- 3: collect candidates, skipping pruned chunks ----------
__global__ __launch_bounds__(256) void collect_kernel(const float* __restrict__ cls) {
    const int n = blockIdx.y;
    const unsigned pivot_base = (unsigned)g_pivot[n] << BIN_SHIFT;
    const int lane = threadIdx.x & 31;
    const int gw = (blockIdx.x * blockDim.x + threadIdx.x) >> 5;
    const int nwarps = (gridDim.x * blockDim.x) >> 5;
    const float4* base = reinterpret_cast<const float4*>(cls + (size_t)n * ACHW);

    for (int g = gw; g < NGROUPS; g += nwarps) {
        int chbase = g * 32;
        int ch_l = chbase + lane;
        bool active = (ch_l < CPI) && (g_chunkmax[n][ch_l] >= pivot_base);
        unsigned act = __ballot_sync(FULLMASK, active);
        while (act) {
            int c = __ffs(act) - 1;
            act &= act - 1;
            int ch = chbase + c;
            const float4* p = base + (size_t)ch * 128;
#pragma unroll
            for (int e = 0; e < 4; e++) {
                float4 v = p[e * 32 + lane];
                float vals[4] = {v.x, v.y, v.z, v.w};
#pragma unroll
                for (int k = 0; k < 4; k++) {
                    float x = vals[k];
                    if (x > THRESH_LOGIT) {
                        unsigned mono = mono_of(x);
                        if (mono >= pivot_base) {
                            int m   = ch * CHUNK + (e * 32 + lane) * 4 + k;
                            int a   = m / CHW_;
                            int rem = m - a * CHW_;
                            int c2  = rem / HW_;
                            int hw  = rem - c2 * HW_;
                            unsigned ref_idx = (unsigned)((hw * A_ + a) * C_ + c2);
                            int pos = atomicAdd(&g_count[n], 1);
                            if (pos < SCAP)
                                g_cand[n][pos] =
                                    ((unsigned long long)mono << 32) |
                                    (0xFFFFFFFFu - ref_idx);
                        }
                    }
                }
            }
        }
    }
}

// ------- 4: enumeration-sort rank (8 threads/candidate) + decode ----------
// rank_i = #{j : key_j > key_i}; keys are unique, so ranks are a bijection.
__global__ __launch_bounds__(128) void rank_decode_kernel(
        const float* __restrict__ reg, const float* __restrict__ anchors) {
    __shared__ unsigned long long sk[SCAP];
    const int n = blockIdx.y;
    int cnt = g_count[n];
    if (cnt > SCAP) cnt = SCAP;
    const int blk_lo = blockIdx.x * CAND_PER_BLK;
    if (blk_lo >= cnt && blk_lo >= TOPN) return;

    const int tid  = threadIdx.x;
    const int cand = blk_lo + (tid >> 3);
    const int sub  = tid & 7;

    // default fill for slots [cnt, TOPN)
    if (cand >= cnt && cand < TOPN && sub == 0) {
        g_boxes[n][cand][0] = 0.f; g_boxes[n][cand][1] = 0.f;
        g_boxes[n][cand][2] = 0.f; g_boxes[n][cand][3] = 0.f;
        g_scores[n][cand] = -1.0f;
        g_labels[n][cand] = 0;
        g_obox[n][cand] = make_float4(0.f, 0.f, 0.f, 0.f);
        g_area[n][cand] = 1.0f;
    }
    if (blk_lo >= cnt) return;   // fill-only block

    for (int i = tid; i < cnt; i += 128)
        sk[i] = g_cand[n][i];
    __syncthreads();

    if (cand >= cnt) return;
    const unsigned long long mykey = sk[cand];
    int r0 = 0, r1 = 0, r2 = 0, r3 = 0;
    int j = sub;
    for (; j + 24 < cnt; j += 32) {
        r0 += (sk[j]      > mykey);
        r1 += (sk[j + 8]  > mykey);
        r2 += (sk[j + 16] > mykey);
        r3 += (sk[j + 24] > mykey);
    }
    for (; j < cnt; j += 8) r0 += (sk[j] > mykey);
    int r = r0 + r1 + r2 + r3;
    r += __shfl_down_sync(FULLMASK, r, 4, 8);
    r += __shfl_down_sync(FULLMASK, r, 2, 8);
    r += __shfl_down_sync(FULLMASK, r, 1, 8);
    if (sub != 0) return;
    const int rank = r;
    if (rank >= TOPN) return;

    // decode
    unsigned mono = (unsigned)(mykey >> 32);
    unsigned bits = (mono & 0x80000000u) ? (mono ^ 0x80000000u) : ~mono;
    float logit = __uint_as_float(bits);
    float score = 1.0f / (1.0f + expf(-logit));

    unsigned ref_idx = 0xFFFFFFFFu - (unsigned)(mykey & 0xFFFFFFFFull);
    int c   = (int)(ref_idx % C_);
    int loc = (int)(ref_idx / C_);
    int a   = loc % A_;
    int hw  = loc / A_;

    const float* anc = anchors + 4 * (size_t)loc;
    float ax1 = anc[0], ay1 = anc[1], ax2 = anc[2], ay2 = anc[3];
    float wdt = ax2 - ax1 + 1.0f;
    float hgt = ay2 - ay1 + 1.0f;
    float ctrx = ax1 + 0.5f * wdt;
    float ctry = ay1 + 0.5f * hgt;

    size_t rb = (size_t)n * REG_PER_IMG + (size_t)a * 4 * HW_ + hw;
    float dx = reg[rb]               / 10.0f;
    float dy = reg[rb + HW_]         / 10.0f;
    float dw = fminf(reg[rb + 2 * HW_] / 5.0f, BBOX_CLIP);
    float dh = fminf(reg[rb + 3 * HW_] / 5.0f, BBOX_CLIP);

    float pcx = dx * wdt + ctrx;
    float pcy = dy * hgt + ctry;
    float pw  = expf(dw) * wdt;
    float ph  = expf(dh) * hgt;

    float x1 = pcx - 0.5f * pw;
    float y1 = pcy - 0.5f * ph;
    float x2 = pcx + 0.5f * pw - 1.0f;
    float y2 = pcy + 0.5f * ph - 1.0f;
    x1 = fminf(fmaxf(x1, 0.0f), IMW1);
    y1 = fminf(fmaxf(y1, 0.0f), IMH1);
    x2 = fminf(fmaxf(x2, 0.0f), IMW1);
    y2 = fminf(fmaxf(y2, 0.0f), IMH1);

    bool valid = (score > 0.0f) &&
                 (x2 - x1 + 1.0f >= 0.0f) &&
                 (y2 - y1 + 1.0f >= 0.0f);
    int label = c + 1;

    g_boxes[n][rank][0] = x1; g_boxes[n][rank][1] = y1;
    g_boxes[n][rank][2] = x2; g_boxes[n][rank][3] = y2;
    g_scores[n][rank] = score;
    g_labels[n][rank] = label;
    float off = (float)label * 4096.0f;
    g_obox[n][rank] = make_float4(x1 + off, y1 + off, x2 + off, y2 + off);
    g_area[n][rank] = (x2 - x1 + 1.0f) * (y2 - y1 + 1.0f);
    if (valid) atomicOr(&g_validmask[n][rank >> 5], 1u << (rank & 31));
}

// ---------------- 5: IoU > 0.5 bitmask --------------------------------
__global__ void iou_kernel() {
    const int lane = threadIdx.x;
    const int i    = blockIdx.x * blockDim.y + threadIdx.y;
    const int word = blockIdx.y;
    const int n    = blockIdx.z;
    if (i >= TOPN) return;
    int j  = word * 32 + lane;
    int jc = (j < TOPN) ? j : (TOPN - 1);

    float4 bi = g_obox[n][i];  float ai = g_area[n][i];
    float4 bj = g_obox[n][jc]; float aj = g_area[n][jc];

    float iw = fmaxf(fminf(bi.z, bj.z) - fmaxf(bi.x, bj.x) + 1.0f, 0.0f);
    float ih = fmaxf(fminf(bi.w, bj.w) - fmaxf(bi.y, bj.y) + 1.0f, 0.0f);
    float inter = iw * ih;
    float iou = inter / (ai + aj - inter);
    bool cond = (j < TOPN) && (iou > NMS_T);
    unsigned bal = __ballot_sync(FULLMASK, cond);
    if (lane == 0) g_iou[n][i][word] = bal;
}

// -------- 6: serial NMS scan (warp 0) + final top-100 emit + reset --------
__global__ __launch_bounds__(1024) void nms_emit_kernel(float* __restrict__ out) {
    __shared__ unsigned s_keepw[32];
    __shared__ int s_warpoff[32];
    __shared__ int s_tot;
    const int n = blockIdx.x;
    const int tid = threadIdx.x;
    const int lane = tid & 31, w = tid >> 5;

    if (tid < 32) s_keepw[tid] = 0u;
    __syncthreads();

    // warp 0: sequential greedy scan with prefetch + early exit
    if (tid < 32) {
        unsigned supp = 0u;
        unsigned vmw  = g_validmask[n][lane];
        const unsigned* __restrict__ M = &g_iou[n][0][0];
        int kept = 0;
        bool early = false;

        unsigned mN[32];
#pragma unroll
        for (int j = 0; j < 32; j++) mN[j] = M[j * 32 + lane];

#pragma unroll 1
        for (int c = 0; c < 32; c++) {
            unsigned m[32];
#pragma unroll
            for (int j = 0; j < 32; j++) m[j] = mN[j];
            if (c < 31) {
#pragma unroll
                for (int j = 0; j < 32; j++) mN[j] = M[((c + 1) * 32 + j) * 32 + lane];
            }
            unsigned cur = __shfl_sync(FULLMASK, supp, c);
            unsigned vw  = __shfl_sync(FULLMASK, vmw, c);
            unsigned vals[32];
#pragma unroll
            for (int j = 0; j < 32; j++) vals[j] = __shfl_sync(FULLMASK, m[j], c);

            unsigned keepw = 0u;
#pragma unroll
            for (int j = 0; j < 32; j++) {
                unsigned ki = (vw >> j) & (~(cur >> j)) & 1u;
                keepw |= ki << j;
                unsigned msk = 0u - ki;
                cur  |= vals[j] & msk;
                supp |= m[j]    & msk;
            }
            if (lane == 0) s_keepw[c] = keepw;
            kept += __popc(keepw);
            if (kept >= POSTN) { early = true; break; }
        }
        if (lane == 0) s_tot = early ? TOPN : kept;
    }
    __syncthreads();

    // parallel ranking: kept (in order), then non-kept (in order)
    const bool in = tid < TOPN;
    int k = (in && ((s_keepw[w] >> lane) & 1u)) ? 1 : 0;
    unsigned wb = __ballot_sync(FULLMASK, k);
    int pre = __popc(wb & ((1u << lane) - 1u));
    if (lane == 0) s_warpoff[w] = __popc(wb);
    __syncthreads();
    if (tid == 0) {
        int s = 0;
        for (int x = 0; x < 32; x++) { int t2 = s_warpoff[x]; s_warpoff[x] = s; s += t2; }
    }
    __syncthreads();

    if (in) {
        int kept_before = s_warpoff[w] + pre;
        int r = k ? kept_before : (s_tot + (tid - kept_before));
        if (r < POSTN) {
            int base_b = n * POSTN * 4;
            int base_s = N_IMG * POSTN * 4 + n * POSTN;
            int base_l = N_IMG * POSTN * 5 + n * POSTN;
            out[base_b + r * 4 + 0] = g_boxes[n][tid][0];
            out[base_b + r * 4 + 1] = g_boxes[n][tid][1];
            out[base_b + r * 4 + 2] = g_boxes[n][tid][2];
            out[base_b + r * 4 + 3] = g_boxes[n][tid][3];
            out[base_s + r] = k ? g_scores[n][tid] : -1.0f;
            out[base_l + r] = k ? (float)g_labels[n][tid] : 0.0f;
        }
    }

    // reset per-replay state for the next graph replay
    for (int i = tid; i < NBINS; i += 1024) g_hist[n][i] = 0u;
    if (tid < 32) g_validmask[n][tid] = 0u;
    if (tid == 0) g_count[n] = 0;
}

// ---------------- host launch ----------------
extern "C" void kernel_launch(void* const* d_in, const int* in_sizes, int n_in,
                              void* d_out, int out_size) {
    (void)in_sizes; (void)n_in; (void)out_size;
    const float* box_cls = (const float*)d_in[0];
    const float* box_reg = (const float*)d_in[1];
    const float* anchors = (const float*)d_in[2];
    float* out = (float*)d_out;

    hist_kernel<<<dim3(334, N_IMG), 256>>>(box_cls);
    pivot_kernel<<<1, 256>>>();
    collect_kernel<<<dim3(74, N_IMG), 256>>>(box_cls);
    rank_decode_kernel<<<dim3(RANK_GRID, N_IMG), 128>>>(box_reg, anchors);
    iou_kernel<<<dim3(125, 32, N_IMG), dim3(32, 8)>>>();
    nms_emit_kernel<<<N_IMG, 1024>>>(out);
}